// round 15
// baseline (speedup 1.0000x reference)
#include <cuda_runtime.h>
#include <cuda_fp16.h>
#include <cstdint>

// ImageWarped: trilinear sampling of [B,128,128,128,1] fp32 at [B,N,3] coords.
// B=2, N=2097152.
//
// R15: single persistent kernel = pack phase + software grid barrier +
// sample phase. Removes the second launch boundary/ramp (the last ~3-5us
// of non-floor time; sample is at the L1tex within-LDG replay floor and
// pack near its coalesced-wavefront floor).
//
//  - 592 blocks (4/SM on 148 SMs), 256 threads, guaranteed co-resident
//    -> spin barrier is deadlock-free.
//  - Barrier: monotonic ticket counter, epoch = ticket/gridDim; works
//    unchanged across graph replays (no reset).
//  - Pack: scalar 2x2x2 fp16 cube -> uint4 (evict-last hint), grid-stride.
//  - Sample: ONE scattered 16B ld.nc gather per sample, 2 samples/thread,
//    grid/out evict-first streaming, grid-stride.
//  - ld.nc after the barrier is safe: no g_packed line is read pre-barrier,
//    so no stale L1 lines can exist; pack stores are made visible via
//    __threadfence() + atomic ticket (release/acquire pattern).
//
// fp16 quantization -> rel_err ~2.1e-4 (< 1e-3 gate, verified R3-R14).
// Out-of-range "+1" neighbors are weight-masked (exactly-zero fractional
// weights per the reference floor/ceil convention).

#define BATCH 2
#define NPTS  2097152
#define HVOX  (128 * 128 * 128)
#define VOXELS (BATCH * HVOX)
#define CLAMP_LO 0.001f
#define CLAMP_HI 126.999f

#define NBLOCKS      592                       // 4 per SM * 148 SMs
#define PACK_UNITS   (VOXELS / 256)            // 16384
#define SAMPLE_UNITS (BATCH * NPTS / 2 / 256)  // 8192

__device__ uint4 g_packed[VOXELS];             // 64 MB scratch
__device__ unsigned long long g_barrier_ctr;   // zero-initialized, monotonic

__device__ __forceinline__ uint32_t pack_h2(float a, float b) {
    __half2 h = __floats2half2_rn(a, b);
    return *reinterpret_cast<uint32_t*>(&h);
}

__device__ __forceinline__ uint64_t mk_evict_last_policy() {
    uint64_t pol;
    asm("createpolicy.fractional.L2::evict_last.b64 %0, 1.0;" : "=l"(pol));
    return pol;
}

__device__ __forceinline__ void st_hint_v4(uint4* p, uint4 v, uint64_t pol) {
    asm volatile("st.global.L2::cache_hint.v4.b32 [%0], {%1,%2,%3,%4}, %5;"
                 :: "l"(p), "r"(v.x), "r"(v.y), "r"(v.z), "r"(v.w), "l"(pol)
                 : "memory");
}

__device__ __forceinline__ uint4 ld_nc_hint_v4(const uint4* p, uint64_t pol) {
    uint4 v;
    asm volatile("ld.global.nc.L2::cache_hint.v4.b32 {%0,%1,%2,%3}, [%4], %5;"
                 : "=r"(v.x), "=r"(v.y), "=r"(v.z), "=r"(v.w)
                 : "l"(p), "l"(pol));
    return v;
}

__device__ __forceinline__ void pack_voxel(const float* __restrict__ image,
                                           int idx, uint64_t pol)
{
    const int z = idx & 127;
    const int y = (idx >> 7) & 127;
    const int x = (idx >> 14) & 127;
    const int dz = (z < 127) ? 1 : 0;
    const int dy = (y < 127) ? 128 : 0;
    const int dx = (x < 127) ? 16384 : 0;

    const float c111 = __ldg(image + idx);
    const float c112 = __ldg(image + idx + dz);
    const float c121 = __ldg(image + idx + dy);
    const float c122 = __ldg(image + idx + dy + dz);
    const float c211 = __ldg(image + idx + dx);
    const float c212 = __ldg(image + idx + dx + dz);
    const float c221 = __ldg(image + idx + dx + dy);
    const float c222 = __ldg(image + idx + dx + dy + dz);

    uint4 p;
    p.x = pack_h2(c111, c112);
    p.y = pack_h2(c121, c122);
    p.z = pack_h2(c211, c212);
    p.w = pack_h2(c221, c222);
    st_hint_v4(&g_packed[idx], p, pol);
}

__device__ __forceinline__ float sample_one(float gx, float gy, float gz,
                                            int base_b, uint64_t pol)
{
    const float x = fminf(fmaxf(gx * 128.0f, CLAMP_LO), CLAMP_HI);
    const float y = fminf(fmaxf(gy * 128.0f, CLAMP_LO), CLAMP_HI);
    const float z = fminf(fmaxf(gz * 128.0f, CLAMP_LO), CLAMP_HI);

    const float x1f = floorf(x), x2f = ceilf(x);
    const float y1f = floorf(y), y2f = ceilf(y);
    const float z1f = floorf(z), z2f = ceilf(z);

    const int cube = base_b + (((int)x1f) << 14) + (((int)y1f) << 7) + (int)z1f;
    const uint4 p = ld_nc_hint_v4(&g_packed[cube], pol);

    const float2 a1 = __half22float2(*reinterpret_cast<const __half2*>(&p.x)); // c111,c112
    const float2 a2 = __half22float2(*reinterpret_cast<const __half2*>(&p.y)); // c121,c122
    const float2 b1 = __half22float2(*reinterpret_cast<const __half2*>(&p.z)); // c211,c212
    const float2 b2 = __half22float2(*reinterpret_cast<const __half2*>(&p.w)); // c221,c222

    const float wx = x - x1f, wx2 = x2f - x;
    const float wy = y - y1f, wy2 = y2f - y;
    const float wz = z - z1f, wz2 = z2f - z;

    const float lerp_y1 = (b1.x * wx + a1.x * wx2) * wy2
                        + (b2.x * wx + a2.x * wx2) * wy;
    const float lerp_y2 = (b1.y * wx + a1.y * wx2) * wy2
                        + (b2.y * wx + a2.y * wx2) * wy;
    return lerp_y2 * wz + lerp_y1 * wz2;
}

__global__ void __launch_bounds__(256, 4)
fused_kernel(const float* __restrict__ image,
             const float* __restrict__ grid,
             float* __restrict__ out)
{
    const uint64_t pol = mk_evict_last_policy();
    const int tid = threadIdx.x;

    // ---- Phase 1: pack (grid-stride over 16384 block-units) ----
    for (int u = blockIdx.x; u < PACK_UNITS; u += NBLOCKS)
        pack_voxel(image, u * 256 + tid, pol);

    // ---- Grid barrier (replay-safe monotonic ticket) ----
    __threadfence();                       // make pack stores visible (release)
    __syncthreads();                       // all threads of block done packing
    __shared__ unsigned long long s_go;
    if (tid == 0) {
        unsigned long long ticket = atomicAdd(&g_barrier_ctr, 1ULL);
        unsigned long long target = (ticket / NBLOCKS + 1ULL) * NBLOCKS;
        while (atomicAdd(&g_barrier_ctr, 0ULL) < target)
            __nanosleep(128);
        s_go = 1;
    }
    __syncthreads();                       // block released
    __threadfence();                       // acquire

    // ---- Phase 2: sample (grid-stride over 8192 block-units) ----
    for (int u = blockIdx.x; u < SAMPLE_UNITS; u += NBLOCKS) {
        const int t = u * 256 + tid;       // 2 samples per thread
        const int s = t << 1;
        const int base_b = (s >> 21) << 21;

        const float2* g = (const float2*)(grid + 3 * (size_t)s);
        const float2 q0 = __ldcs(g + 0);   // x0 y0
        const float2 q1 = __ldcs(g + 1);   // z0 x1
        const float2 q2 = __ldcs(g + 2);   // y1 z1

        float2 r;
        r.x = sample_one(q0.x, q0.y, q1.x, base_b, pol);
        r.y = sample_one(q1.y, q2.x, q2.y, base_b, pol);
        __stcs((float2*)(out + s), r);
    }
}

extern "C" void kernel_launch(void* const* d_in, const int* in_sizes, int n_in,
                              void* d_out, int out_size)
{
    const float* image = (const float*)d_in[0];
    const float* grid  = (const float*)d_in[1];
    float* out = (float*)d_out;

    fused_kernel<<<NBLOCKS, 256>>>(image, grid, out);
}